// round 1
// baseline (speedup 1.0000x reference)
#include <cuda_runtime.h>
#include <cuda_bf16.h>

#define NPRI   8732
#define NCLS   21
#define NBATCH 8
#define TOPK   200
#define MCAND  600
#define CAP    1024          // power of two >= worst-case passer count (mean 437, sigma 20)
#define CONF_TH 0.95f
#define NMS_TH  0.45f
#define NTHREADS 256

__global__ void __launch_bounds__(NTHREADS)
detect_kernel(const float* __restrict__ loc,
              const float* __restrict__ conf,
              float* __restrict__ out)
{
    const int lane = blockIdx.x;          // 0..167
    const int b = lane / NCLS;
    const int c = lane % NCLS;
    float* outp = out + (size_t)lane * TOPK * 5;
    const int tid = threadIdx.x;

    // background class: all zeros
    if (c == 0) {
        for (int i = tid; i < TOPK * 5; i += NTHREADS) outp[i] = 0.0f;
        return;
    }

    __shared__ unsigned long long key[CAP];
    __shared__ float bx1[MCAND], by1[MCAND], bx2[MCAND], by2[MCAND], barea[MCAND];
    __shared__ unsigned char supp[MCAND];
    __shared__ short rnk[MCAND];
    __shared__ int s_count, s_fp, s_n;

    if (tid == 0) { s_count = 0; s_fp = 0x7FFFFFFF; }
    __syncthreads();

    // ---- Phase A: collect passers (score, prior index) ----
    const float* confc = conf + (size_t)b * NPRI * NCLS + c;
    for (int p = tid; p < NPRI; p += NTHREADS) {
        float s = confc[(size_t)p * NCLS];
        if (s > CONF_TH) {
            int pos = atomicAdd(&s_count, 1);
            if (pos < CAP) {
                // descending sort key: score (positive float -> monotone bits) major,
                // ~idx minor => ties broken by LOWER index first (lax.top_k semantics)
                key[pos] = ((unsigned long long)__float_as_uint(s) << 32)
                         | (unsigned)(0xFFFFFFFFu - (unsigned)p);
            }
            atomicMin(&s_fp, p);
        }
    }
    __syncthreads();
    const int count = min(s_count, CAP);
    for (int i = count + tid; i < CAP; i += NTHREADS) key[i] = 0ull;  // pad sorts last
    __syncthreads();

    // ---- Phase B: bitonic sort, descending ----
    for (int k = 2; k <= CAP; k <<= 1) {
        for (int j = k >> 1; j > 0; j >>= 1) {
            for (int i = tid; i < CAP; i += NTHREADS) {
                int l = i ^ j;
                if (l > i) {
                    unsigned long long a = key[i], bb = key[l];
                    bool asc = (i & k) != 0;   // descending overall
                    if ((!asc && a < bb) || (asc && a > bb)) {
                        key[i] = bb; key[l] = a;
                    }
                }
            }
            __syncthreads();
        }
    }

    const int M = min(count, MCAND);

    // ---- Phase C: gather candidate boxes ----
    for (int t = tid; t < M; t += NTHREADS) {
        int p = (int)(0xFFFFFFFFu - (unsigned)(key[t] & 0xFFFFFFFFu));
        const float* L = loc + ((size_t)b * NPRI + p) * 4;
        float x1 = L[0], y1 = L[1], x2 = L[2], y2 = L[3];
        bx1[t] = x1; by1[t] = y1; bx2[t] = x2; by2[t] = y2;
        barea[t] = (x2 - x1) * (y2 - y1);
        supp[t] = 0;
    }
    __syncthreads();

    // ---- Phase D: greedy NMS (serial over i, parallel over j) ----
    for (int i = 0; i < M; i++) {
        __syncthreads();
        if (supp[i]) continue;
        float xi1 = bx1[i], yi1 = by1[i], xi2 = bx2[i], yi2 = by2[i], ai = barea[i];
        for (int j = i + 1 + tid; j < M; j += NTHREADS) {
            if (supp[j]) continue;
            float xx1 = fmaxf(xi1, bx1[j]);
            float yy1 = fmaxf(yi1, by1[j]);
            float xx2 = fminf(xi2, bx2[j]);
            float yy2 = fminf(yi2, by2[j]);
            float iw = fmaxf(xx2 - xx1, 0.0f);
            float ih = fmaxf(yy2 - yy1, 0.0f);
            float inter = iw * ih;
            // IEEE division regardless of fast-math flags (decision boundary!)
            float iou = __fdiv_rn(inter, ai + barea[j] - inter);
            if (iou > NMS_TH) supp[j] = 1;
        }
    }
    __syncthreads();

    // ---- Phase E: stable rank of kept candidates ----
    if (tid == 0) {
        int n = 0;
        for (int j = 0; j < M; j++) {
            rnk[j] = supp[j] ? (short)-1 : (short)n;
            if (!supp[j]) n++;
        }
        s_n = n < TOPK ? n : TOPK;
    }
    __syncthreads();
    const int n = s_n;

    if (count == 0) {
        // no passers at all -> entire lane zero
        for (int i = tid; i < TOPK * 5; i += NTHREADS) outp[i] = 0.0f;
        return;
    }

    // kept slots
    for (int j = tid; j < M; j += NTHREADS) {
        int r = rnk[j];
        if (r >= 0 && r < TOPK) {
            float s = __uint_as_float((unsigned)(key[j] >> 32));
            float* o = outp + r * 5;
            o[0] = s; o[1] = bx1[j]; o[2] = by1[j]; o[3] = bx2[j]; o[4] = by2[j];
        }
    }
    // tail slots: score 0, box of first passing prior
    {
        const float* L = loc + ((size_t)b * NPRI + s_fp) * 4;
        float fx1 = L[0], fy1 = L[1], fx2 = L[2], fy2 = L[3];
        for (int r = n + tid; r < TOPK; r += NTHREADS) {
            float* o = outp + r * 5;
            o[0] = 0.0f; o[1] = fx1; o[2] = fy1; o[3] = fx2; o[4] = fy2;
        }
    }
}

extern "C" void kernel_launch(void* const* d_in, const int* in_sizes, int n_in,
                              void* d_out, int out_size)
{
    const float* loc  = (const float*)d_in[0];   // [8, 8732, 4]
    const float* conf = (const float*)d_in[1];   // [8, 8732, 21]
    // d_in[2] = prior_data: unused by the reference computation
    float* out = (float*)d_out;                  // [8, 21, 200, 5]
    detect_kernel<<<NBATCH * NCLS, NTHREADS>>>(loc, conf, out);
}

// round 2
// speedup vs baseline: 1.3822x; 1.3822x over previous
#include <cuda_runtime.h>
#include <cuda_bf16.h>

#define NPRI   8732
#define NPRI_RND 8960          // 35 * 256, so all threads iterate uniformly (ballot-safe)
#define NCLS   21
#define NBATCH 8
#define TOPK   200
#define MCAND  600
#define NW     19              // ceil(MCAND / 32)
#define CAP    1024            // pow2 >= worst-case passer count (mean 437, sigma 20)
#define CONF_TH 0.95f
#define NMS_TH  0.45f
#define NTHREADS 256

struct __align__(16) Smem {
    float4             box[MCAND];
    unsigned long long key[CAP];
    unsigned           mask[MCAND * NW];
    float              area[MCAND];
    short              sel[TOPK];
    int                count, fp, nkept;
};

__global__ void __launch_bounds__(NTHREADS)
detect_kernel(const float* __restrict__ loc,
              const float* __restrict__ conf,
              float* __restrict__ out)
{
    extern __shared__ unsigned char smem_raw[];
    Smem& S = *reinterpret_cast<Smem*>(smem_raw);

    const int lane_id = blockIdx.x;        // 0..167
    const int b = lane_id / NCLS;
    const int c = lane_id % NCLS;
    float* outp = out + (size_t)lane_id * TOPK * 5;
    const int tid  = threadIdx.x;
    const int lane = tid & 31;
    const int warp = tid >> 5;

    if (c == 0) {   // background class: all zeros
        for (int i = tid; i < TOPK * 5; i += NTHREADS) outp[i] = 0.0f;
        return;
    }

    if (tid == 0) { S.count = 0; S.fp = 0x7FFFFFFF; }
    __syncthreads();

    // ---- Phase A: collect passers, warp-aggregated push ----
    const float* confc = conf + (size_t)b * NPRI * NCLS + c;
    for (int p = tid; p < NPRI_RND; p += NTHREADS) {
        bool in = p < NPRI;
        float s = in ? __ldg(&confc[(size_t)p * NCLS]) : 0.0f;
        bool pass = in && (s > CONF_TH);
        unsigned m = __ballot_sync(0xFFFFFFFFu, pass);
        if (m) {
            int leader = __ffs(m) - 1;
            int base = 0;
            if (lane == leader) {
                base = atomicAdd(&S.count, __popc(m));
                atomicMin(&S.fp, p);          // leader has lowest p in this warp-chunk
            }
            base = __shfl_sync(0xFFFFFFFFu, base, leader);
            if (pass) {
                int pos = base + __popc(m & ((1u << lane) - 1u));
                if (pos < CAP) {
                    // score major (desc), ~idx minor => ties broken by lower index
                    S.key[pos] = ((unsigned long long)__float_as_uint(s) << 32)
                               | (unsigned)(0xFFFFFFFFu - (unsigned)p);
                }
            }
        }
    }
    __syncthreads();

    const int count = min(S.count, CAP);
    if (count == 0) {  // nothing passed -> zero lane
        for (int i = tid; i < TOPK * 5; i += NTHREADS) outp[i] = 0.0f;
        return;
    }

    // ---- Phase B: bitonic sort (descending), dynamic pow2 size ----
    const int n2 = (count <= 1) ? 1 : (1 << (32 - __clz(count - 1)));
    for (int i = count + tid; i < n2; i += NTHREADS) S.key[i] = 0ull;
    for (int k = 2; k <= n2; k <<= 1) {
        for (int j = k >> 1; j > 0; j >>= 1) {
            __syncthreads();
            for (int i = tid; i < n2; i += NTHREADS) {
                int l = i ^ j;
                if (l > i) {
                    unsigned long long a = S.key[i], bb = S.key[l];
                    if (((i & k) == 0) ? (a < bb) : (a > bb)) {
                        S.key[i] = bb; S.key[l] = a;
                    }
                }
            }
        }
    }
    __syncthreads();

    const int M = min(count, MCAND);

    // ---- Phase C: gather candidate boxes (sorted order) ----
    for (int t = tid; t < M; t += NTHREADS) {
        int p = (int)(0xFFFFFFFFu - (unsigned)(S.key[t] & 0xFFFFFFFFu));
        float4 L = __ldg((const float4*)(loc + ((size_t)b * NPRI + p) * 4));
        S.box[t]  = L;
        S.area[t] = (L.z - L.x) * (L.w - L.y);
    }
    __syncthreads();

    // ---- Phase D: IoU adjacency bitmask (fully parallel, no barriers) ----
    // Warp g handles rows [g*32, g*32+32); lane owns one row; inner loop over j
    // uses broadcast LDS of box_j. mask[i][w] bit t => IoU(i, w*32+t) > TH and j > i.
    const int ngroups = (M + 31) >> 5;
    for (int g = warp; g < ngroups; g += NTHREADS / 32) {
        const int i = g * 32 + lane;
        const bool rowvalid = i < M;
        float4 bi = rowvalid ? S.box[i] : make_float4(0, 0, 0, 0);
        float  ai = rowvalid ? S.area[i] : 0.0f;
        for (int w = 0; w < NW; ++w) {
            unsigned bits = 0;
            if (w >= g) {
                const int j0 = w * 32;
                const int jmax = min(32, M - j0);
                #pragma unroll 4
                for (int t2 = 0; t2 < jmax; ++t2) {
                    int j = j0 + t2;
                    float4 bj = S.box[j];          // broadcast (all lanes same j)
                    float  aj = S.area[j];
                    float xx1 = fmaxf(bi.x, bj.x);
                    float yy1 = fmaxf(bi.y, bj.y);
                    float xx2 = fminf(bi.z, bj.z);
                    float yy2 = fminf(bi.w, bj.w);
                    float inter = fmaxf(xx2 - xx1, 0.0f) * fmaxf(yy2 - yy1, 0.0f);
                    // IEEE division — decision boundary must match reference exactly
                    float iou = __fdiv_rn(inter, ai + aj - inter);
                    if ((iou > NMS_TH) && (j > i)) bits |= (1u << t2);
                }
            }
            if (rowvalid) S.mask[i * NW + w] = bits;
        }
    }
    __syncthreads();

    // ---- Phase E: greedy sweep, single warp, supp words in registers ----
    if (warp == 0) {
        unsigned suppw = 0;
        unsigned m = (lane < NW) ? S.mask[lane] : 0u;   // row 0 prefetched
        int kept = 0;
        for (int i = 0; i < M && kept < TOPK; ++i) {
            unsigned mn = (lane < NW && (i + 1) < M) ? S.mask[(i + 1) * NW + lane] : 0u;
            unsigned ow = __shfl_sync(0xFFFFFFFFu, suppw, i >> 5);
            if (!((ow >> (i & 31)) & 1u)) {
                suppw |= m;
                if (lane == 0) S.sel[kept] = (short)i;
                kept++;
            }
            m = mn;
        }
        if (lane == 0) S.nkept = kept;   // == min(total_kept, TOPK) by construction
    }
    __syncthreads();

    // ---- Phase F: output ----
    const int n = S.nkept;
    const int fp = S.fp;
    for (int r = tid; r < TOPK; r += NTHREADS) {
        float4 bb; float sc;
        if (r < n) {
            int i = S.sel[r];
            sc = __uint_as_float((unsigned)(S.key[i] >> 32));
            bb = S.box[i];
        } else {
            sc = 0.0f;
            bb = __ldg((const float4*)(loc + ((size_t)b * NPRI + fp) * 4));
        }
        float* o = outp + r * 5;
        o[0] = sc; o[1] = bb.x; o[2] = bb.y; o[3] = bb.z; o[4] = bb.w;
    }
}

extern "C" void kernel_launch(void* const* d_in, const int* in_sizes, int n_in,
                              void* d_out, int out_size)
{
    const float* loc  = (const float*)d_in[0];   // [8, 8732, 4]
    const float* conf = (const float*)d_in[1];   // [8, 8732, 21]
    // d_in[2] = prior_data: unused by the reference computation
    float* out = (float*)d_out;                  // [8, 21, 200, 5]

    cudaFuncSetAttribute(detect_kernel,
                         cudaFuncAttributeMaxDynamicSharedMemorySize,
                         (int)sizeof(Smem));
    detect_kernel<<<NBATCH * NCLS, NTHREADS, sizeof(Smem)>>>(loc, conf, out);
}

// round 3
// speedup vs baseline: 2.2339x; 1.6162x over previous
#include <cuda_runtime.h>
#include <cuda_bf16.h>

#define NPRI   8732
#define NCLS   21
#define NBATCH 8
#define TOPK   200
#define MCAND  600
#define NW     19              // ceil(MCAND / 32)
#define CAP    1024            // pow2 >= worst-case passer count (mean 437, sigma 20)
#define CONF_TH 0.95f
#define NMS_TH  0.45f
#define NTHREADS 512
#define NWARPS  16

struct __align__(16) Smem {
    float4             box[MCAND];
    unsigned long long key[CAP];
    unsigned           mask[MCAND * NW];
    float              area[MCAND];
    short              sel[TOPK];
    int                count, fp, nkept;
};

__global__ void __launch_bounds__(NTHREADS)
detect_kernel(const float* __restrict__ loc,
              const float* __restrict__ conf,
              float* __restrict__ out)
{
    extern __shared__ unsigned char smem_raw[];
    Smem& S = *reinterpret_cast<Smem*>(smem_raw);

    const int lane_id = blockIdx.x;        // 0..167
    const int b = lane_id / NCLS;
    const int c = lane_id % NCLS;
    float* outp = out + (size_t)lane_id * TOPK * 5;
    const int tid  = threadIdx.x;
    const int lane = tid & 31;
    const int warp = tid >> 5;

    if (c == 0) {   // background class: all zeros
        for (int i = tid; i < TOPK * 5; i += NTHREADS) outp[i] = 0.0f;
        return;
    }

    if (tid == 0) { S.count = 0; S.fp = 0x7FFFFFFF; }
    __syncthreads();

    // ---- Phase A: collect passers; 6-deep preloads break the load->ballot chain ----
    const float* confc = conf + (size_t)b * NPRI * NCLS + c;
    for (int base = 0; base < 18; base += 6) {           // 18*512 = 9216 >= 8732
        float sv[6];
        #pragma unroll
        for (int t = 0; t < 6; ++t) {
            int p = tid + (base + t) * NTHREADS;
            sv[t] = (p < NPRI) ? __ldg(&confc[(size_t)p * NCLS]) : 0.0f;
        }
        #pragma unroll
        for (int t = 0; t < 6; ++t) {
            int p = tid + (base + t) * NTHREADS;
            bool pass = sv[t] > CONF_TH;                 // p>=NPRI has sv=0 -> false
            unsigned m = __ballot_sync(0xFFFFFFFFu, pass);
            if (m) {
                int leader = __ffs(m) - 1;
                int basep = 0;
                if (lane == leader) {
                    basep = atomicAdd(&S.count, __popc(m));
                    atomicMin(&S.fp, p);                 // leader = lowest p this ballot
                }
                basep = __shfl_sync(0xFFFFFFFFu, basep, leader);
                if (pass) {
                    int pos = basep + __popc(m & ((1u << lane) - 1u));
                    if (pos < CAP)
                        S.key[pos] = ((unsigned long long)__float_as_uint(sv[t]) << 32)
                                   | (unsigned)(0xFFFFFFFFu - (unsigned)p);
                }
            }
        }
    }
    __syncthreads();

    const int count = min(S.count, CAP);
    if (count == 0) {
        for (int i = tid; i < TOPK * 5; i += NTHREADS) outp[i] = 0.0f;
        return;
    }

    // ---- Phase B: bitonic sort (descending) over next pow2 ----
    const int n2 = (count <= 1) ? 1 : (1 << (32 - __clz(count - 1)));
    for (int i = count + tid; i < n2; i += NTHREADS) S.key[i] = 0ull;
    for (int k = 2; k <= n2; k <<= 1) {
        for (int j = k >> 1; j > 0; j >>= 1) {
            __syncthreads();
            for (int i = tid; i < n2; i += NTHREADS) {
                int l = i ^ j;
                if (l > i) {
                    unsigned long long a = S.key[i], bb = S.key[l];
                    if (((i & k) == 0) ? (a < bb) : (a > bb)) {
                        S.key[i] = bb; S.key[l] = a;
                    }
                }
            }
        }
    }
    __syncthreads();

    const int M = min(count, MCAND);
    const int ngroups = (M + 31) >> 5;

    // ---- Phase C: gather candidate boxes (sorted order) ----
    for (int t = tid; t < M; t += NTHREADS) {
        int p = (int)(0xFFFFFFFFu - (unsigned)(S.key[t] & 0xFFFFFFFFu));
        float4 L = __ldg((const float4*)(loc + ((size_t)b * NPRI + p) * 4));
        S.box[t]  = L;
        S.area[t] = (L.z - L.x) * (L.w - L.y);
    }
    __syncthreads();

    // ---- Phase D: IoU adjacency bitmask, tiles balanced round-robin over warps ----
    {
        int tcnt = 0;
        for (int g = 0; g < ngroups; ++g) {
            for (int w = g; w < ngroups; ++w, ++tcnt) {
                if ((tcnt & (NWARPS - 1)) != warp) continue;
                const int i = g * 32 + lane;
                const bool rv = i < M;
                float4 bi = rv ? S.box[i] : make_float4(0, 0, 0, 0);
                float  ai = rv ? S.area[i] : 0.0f;
                const int j0 = w * 32;
                const int jmax = min(32, M - j0);
                unsigned bits = 0;
                if (w == g) {
                    #pragma unroll 8
                    for (int t2 = 0; t2 < jmax; ++t2) {
                        int j = j0 + t2;
                        float4 bj = S.box[j];
                        float  aj = S.area[j];
                        float inter = fmaxf(fminf(bi.z, bj.z) - fmaxf(bi.x, bj.x), 0.0f)
                                    * fmaxf(fminf(bi.w, bj.w) - fmaxf(bi.y, bj.y), 0.0f);
                        float iou = __fdiv_rn(inter, ai + aj - inter);  // exact IEEE div
                        if ((iou > NMS_TH) && (j > i)) bits |= (1u << t2);
                    }
                } else {  // all j > i guaranteed
                    #pragma unroll 8
                    for (int t2 = 0; t2 < jmax; ++t2) {
                        int j = j0 + t2;
                        float4 bj = S.box[j];
                        float  aj = S.area[j];
                        float inter = fmaxf(fminf(bi.z, bj.z) - fmaxf(bi.x, bj.x), 0.0f)
                                    * fmaxf(fminf(bi.w, bj.w) - fmaxf(bi.y, bj.y), 0.0f);
                        float iou = __fdiv_rn(inter, ai + aj - inter);
                        if (iou > NMS_TH) bits |= (1u << t2);
                    }
                }
                if (rv) S.mask[i * NW + w] = bits;
            }
        }
    }
    __syncthreads();

    // ---- Phase E: greedy sweep, warp 0, chunked: 1 shfl per 32 candidates ----
    // acc (per lane L): OR of mask[i][L] over kept i (only forward words written).
    if (warp == 0) {
        unsigned acc = 0;
        int kept = 0;
        for (int w = 0; w < ngroups && kept < TOPK; ++w) {
            unsigned cur = __shfl_sync(0xFFFFFFFFu, acc, w);  // supp bits for chunk w
            for (int sub = 0; sub < 4; ++sub) {
                const int ibase = w * 32 + sub * 8;
                if (ibase >= M) break;
                unsigned selfm[8], rowm[8];
                #pragma unroll
                for (int t = 0; t < 8; ++t) {
                    int i = ibase + t;
                    bool v = i < M;
                    selfm[t] = v ? S.mask[i * NW + w] : 0u;                    // broadcast
                    rowm[t]  = (v && lane >= w && lane < ngroups)
                             ? S.mask[i * NW + lane] : 0u;                     // stride-19
                }
                #pragma unroll
                for (int t = 0; t < 8; ++t) {
                    int i = ibase + t;
                    if (i < M && kept < TOPK && !((cur >> ((sub * 8 + t) & 31)) & 1u)) {
                        if (lane == 0) S.sel[kept] = (short)i;
                        kept++;
                        cur |= selfm[t];
                        acc |= rowm[t];
                    }
                }
            }
        }
        if (lane == 0) S.nkept = kept;   // == min(total_kept, TOPK)
    }
    __syncthreads();

    // ---- Phase F: output ----
    const int n = S.nkept;
    const int fp = S.fp;
    for (int r = tid; r < TOPK; r += NTHREADS) {
        float4 bb; float sc;
        if (r < n) {
            int i = S.sel[r];
            sc = __uint_as_float((unsigned)(S.key[i] >> 32));
            bb = S.box[i];
        } else {
            sc = 0.0f;
            bb = __ldg((const float4*)(loc + ((size_t)b * NPRI + fp) * 4));
        }
        float* o = outp + r * 5;
        o[0] = sc; o[1] = bb.x; o[2] = bb.y; o[3] = bb.z; o[4] = bb.w;
    }
}

extern "C" void kernel_launch(void* const* d_in, const int* in_sizes, int n_in,
                              void* d_out, int out_size)
{
    const float* loc  = (const float*)d_in[0];   // [8, 8732, 4]
    const float* conf = (const float*)d_in[1];   // [8, 8732, 21]
    // d_in[2] = prior_data: unused by the reference computation
    float* out = (float*)d_out;                  // [8, 21, 200, 5]

    cudaFuncSetAttribute(detect_kernel,
                         cudaFuncAttributeMaxDynamicSharedMemorySize,
                         (int)sizeof(Smem));
    detect_kernel<<<NBATCH * NCLS, NTHREADS, sizeof(Smem)>>>(loc, conf, out);
}

// round 4
// speedup vs baseline: 3.3746x; 1.5106x over previous
#include <cuda_runtime.h>
#include <cuda_bf16.h>

#define NPRI    8732
#define NCLS    21
#define NBATCH  8
#define NLANES  (NBATCH * NCLS)   // 168
#define TOPK    200
#define MCAND   600
#define NW      19                // ceil(MCAND/32)
#define MPITCH  601               // i-pitch (odd -> conflict-free lane*MPITCH reads)
#define MWORDS  11420             // NW*MPITCH=11419, padded to /4 for uint4 copies
#define CAP     1024
#define CONF_TH 0.95f
#define NMS_TH  0.45f
#define NSPLIT  4

// ---------------- global scratch (static __device__: allowed) ----------------
__device__ float4   g_box[NLANES][MCAND];
__device__ float    g_area[NLANES][MCAND];
__device__ float    g_score[NLANES][MCAND];
__device__ unsigned g_mask[NLANES][MWORDS];
__device__ int      g_count[NLANES];
__device__ int      g_fp[NLANES];

static __device__ __forceinline__ unsigned long long shfl_xor_u64(unsigned long long v, int m) {
    unsigned lo = __shfl_xor_sync(0xFFFFFFFFu, (unsigned)v, m);
    unsigned hi = __shfl_xor_sync(0xFFFFFFFFu, (unsigned)(v >> 32), m);
    return ((unsigned long long)hi << 32) | lo;
}

// ================= K1: collect + sort + gather =================
__global__ void __launch_bounds__(512)
k1_collect_sort(const float* __restrict__ loc, const float* __restrict__ conf)
{
    __shared__ unsigned long long key[CAP];
    __shared__ int s_count, s_fp;
    const int lane_id = blockIdx.x;
    const int b = lane_id / NCLS, c = lane_id % NCLS;
    const int tid = threadIdx.x, lane = tid & 31;
    if (c == 0) return;                       // background handled in K3

    if (tid == 0) { s_count = 0; s_fp = 0x7FFFFFFF; }
    __syncthreads();

    // ---- Phase A: collect passers (6-deep preload, warp-aggregated push) ----
    const float* confc = conf + (size_t)b * NPRI * NCLS + c;
    for (int base = 0; base < 18; base += 6) {          // 18*512 = 9216 >= 8732
        float sv[6];
        #pragma unroll
        for (int t = 0; t < 6; ++t) {
            int p = tid + (base + t) * 512;
            sv[t] = (p < NPRI) ? __ldg(&confc[(size_t)p * NCLS]) : 0.0f;
        }
        #pragma unroll
        for (int t = 0; t < 6; ++t) {
            int p = tid + (base + t) * 512;
            bool pass = sv[t] > CONF_TH;
            unsigned m = __ballot_sync(0xFFFFFFFFu, pass);
            if (m) {
                int leader = __ffs(m) - 1, bp = 0;
                if (lane == leader) {
                    bp = atomicAdd(&s_count, __popc(m));
                    atomicMin(&s_fp, p);                 // leader = lowest p this ballot
                }
                bp = __shfl_sync(0xFFFFFFFFu, bp, leader);
                if (pass) {
                    int pos = bp + __popc(m & ((1u << lane) - 1u));
                    if (pos < CAP)
                        key[pos] = ((unsigned long long)__float_as_uint(sv[t]) << 32)
                                 | (unsigned)(0xFFFFFFFFu - (unsigned)p);
                }
            }
        }
    }
    __syncthreads();
    const int count = min(s_count, CAP);
    if (tid == 0) { g_count[lane_id] = count; g_fp[lane_id] = s_fp; }
    if (count == 0) return;

    // ---- Phase B: descending bitonic sort ----
    if (count <= 512) {
        // hybrid: register/shuffle stages (j<=16), smem stages (j>=32)
        unsigned long long v = (tid < count) ? key[tid] : 0ull;
        #pragma unroll
        for (int k = 2; k <= 32; k <<= 1) {
            #pragma unroll
            for (int j = k >> 1; j; j >>= 1) {
                unsigned long long o = shfl_xor_u64(v, j);
                bool takeMax = (((tid & k) == 0) == ((tid & j) == 0));
                bool gt = v > o;
                v = (takeMax == gt) ? v : o;
            }
        }
        key[tid] = v;
        #pragma unroll
        for (int k = 64; k <= 512; k <<= 1) {
            for (int j = k >> 1; j >= 32; j >>= 1) {
                __syncthreads();
                if ((tid & j) == 0) {
                    int l = tid ^ j;
                    unsigned long long a = key[tid], bb = key[l];
                    if (((tid & k) == 0) ? (a < bb) : (a > bb)) { key[tid] = bb; key[l] = a; }
                }
            }
            __syncthreads();
            v = key[tid];
            const bool up = ((tid & k) == 0);     // uniform per warp (k>=64)
            #pragma unroll
            for (int j = 16; j; j >>= 1) {
                unsigned long long o = shfl_xor_u64(v, j);
                bool takeMax = (up == ((tid & j) == 0));
                bool gt = v > o;
                v = (takeMax == gt) ? v : o;
            }
            key[tid] = v;
        }
        __syncthreads();
    } else {
        // rare path (count in (512,1024]): legacy smem-only sort
        const int n2 = 1 << (32 - __clz(count - 1));
        for (int i = count + tid; i < n2; i += 512) key[i] = 0ull;
        for (int k = 2; k <= n2; k <<= 1) {
            for (int j = k >> 1; j > 0; j >>= 1) {
                __syncthreads();
                for (int i = tid; i < n2; i += 512) {
                    int l = i ^ j;
                    if (l > i) {
                        unsigned long long a = key[i], bb = key[l];
                        if (((i & k) == 0) ? (a < bb) : (a > bb)) { key[i] = bb; key[l] = a; }
                    }
                }
            }
        }
        __syncthreads();
    }

    // ---- Phase C: gather boxes for top-M, publish to global scratch ----
    const int M = min(count, MCAND);
    for (int t = tid; t < M; t += 512) {
        unsigned long long kv = key[t];
        int p = (int)(0xFFFFFFFFu - (unsigned)(kv & 0xFFFFFFFFu));
        float4 L = __ldg((const float4*)(loc + ((size_t)b * NPRI + p) * 4));
        g_box[lane_id][t]   = L;
        g_area[lane_id][t]  = (L.z - L.x) * (L.w - L.y);
        g_score[lane_id][t] = __uint_as_float((unsigned)(kv >> 32));
    }
}

// ================= K2: IoU adjacency bitmask (split over NSPLIT blocks/lane) =================
__global__ void __launch_bounds__(512)
k2_masks()
{
    const int lane_id = blockIdx.x;
    if ((lane_id % NCLS) == 0) return;
    const int M = min(g_count[lane_id], MCAND);
    if (M == 0) return;

    __shared__ float4 sbox[MCAND];
    __shared__ float  sarea[MCAND];
    const int tid = threadIdx.x, lane = tid & 31, warp = tid >> 5;
    for (int t = tid; t < M; t += 512) {
        sbox[t]  = g_box[lane_id][t];
        sarea[t] = g_area[lane_id][t];
    }
    __syncthreads();

    const int ngroups = (M + 31) >> 5;
    const int worker   = blockIdx.y * 16 + warp;
    const int nworkers = NSPLIT * 16;
    int t = 0, next = worker;
    for (int g = 0; g < ngroups; ++g) {
        const int i = g * 32 + lane;
        for (int w = g; w < ngroups; ++w, ++t) {
            if (t != next) continue;
            next += nworkers;
            const bool rv = i < M;
            float4 bi = rv ? sbox[i] : make_float4(0, 0, 0, 0);
            float  ai = rv ? sarea[i] : 0.0f;
            const int j0 = w * 32;
            const int jmax = min(32, M - j0);
            unsigned bits = 0;
            #pragma unroll 8
            for (int t2 = 0; t2 < jmax; ++t2) {
                float4 bj = sbox[j0 + t2];
                float  aj = sarea[j0 + t2];
                float inter = fmaxf(fminf(bi.z, bj.z) - fmaxf(bi.x, bj.x), 0.0f)
                            * fmaxf(fminf(bi.w, bj.w) - fmaxf(bi.y, bj.y), 0.0f);
                float un = ai + aj - inter;
                // fast approximate quotient (<=2 ulp); decision certain outside margin.
                float ia = __fdividef(inter, un);
                float diff = ia - NMS_TH;
                bool sup = diff > 0.0f;
                bool unc = !(fabsf(diff) > 1e-5f + 0x1p-16f * fabsf(ia)); // NaN -> uncertain
                if (__ballot_sync(0xFFFFFFFFu, unc)) {     // rare exact fallback
                    if (unc) sup = (__fdiv_rn(inter, un) > NMS_TH);
                }
                if (sup) bits |= 1u << t2;
            }
            if (w == g) bits &= (0xFFFFFFFEu << lane);     // keep only j > i on diagonal
            if (rv) g_mask[lane_id][w * MPITCH + i] = bits;
        }
    }
}

// ================= K3: greedy sweep + output =================
#define K3_SMEM_MASK   0
#define K3_SMEM_BOX    45680                         // NW*MPITCH*4 rounded to 16
#define K3_SMEM_SCORE  (K3_SMEM_BOX + MCAND * 16)
#define K3_SMEM_SEL    (K3_SMEM_SCORE + MCAND * 4)
#define K3_SMEM_TOTAL  (K3_SMEM_SEL + TOPK * 2 + 16)

__global__ void __launch_bounds__(256)
k3_sweep_out(const float* __restrict__ loc, float* __restrict__ out)
{
    extern __shared__ unsigned char raw[];
    unsigned* smask  = (unsigned*)(raw + K3_SMEM_MASK);
    float4*   sbox   = (float4*)(raw + K3_SMEM_BOX);
    float*    sscore = (float*)(raw + K3_SMEM_SCORE);
    short*    sel    = (short*)(raw + K3_SMEM_SEL);
    __shared__ int s_nkept;

    const int lane_id = blockIdx.x;
    const int b = lane_id / NCLS, c = lane_id % NCLS;
    float* outp = out + (size_t)lane_id * TOPK * 5;
    const int tid = threadIdx.x, lane = tid & 31, warp = tid >> 5;

    if (c == 0) {
        for (int i = tid; i < TOPK * 5; i += 256) outp[i] = 0.0f;
        return;
    }
    const int count = g_count[lane_id];
    if (count == 0) {
        for (int i = tid; i < TOPK * 5; i += 256) outp[i] = 0.0f;
        return;
    }
    const int M = min(count, MCAND);
    const int ngroups = (M + 31) >> 5;

    // bulk copy mask region + boxes + scores into smem
    {
        const uint4* src4 = reinterpret_cast<const uint4*>(g_mask[lane_id]);
        uint4* dst4 = reinterpret_cast<uint4*>(smask);
        const int n4 = (ngroups * MPITCH + 3) >> 2;
        for (int i = tid; i < n4; i += 256) dst4[i] = src4[i];
        for (int t = tid; t < M; t += 256) {
            sbox[t]   = g_box[lane_id][t];
            sscore[t] = g_score[lane_id][t];
        }
    }
    __syncthreads();

    // ---- greedy sweep, warp 0, chunked (1 shfl / 32 candidates) ----
    if (warp == 0) {
        unsigned acc = 0;
        int kept = 0;
        for (int w = 0; w < ngroups && kept < TOPK; ++w) {
            unsigned cur = __shfl_sync(0xFFFFFFFFu, acc, w);
            for (int sub = 0; sub < 4; ++sub) {
                const int ibase = w * 32 + sub * 8;
                if (ibase >= M) break;
                unsigned selfm[8], rowm[8];
                #pragma unroll
                for (int t = 0; t < 8; ++t) {
                    int i = ibase + t;
                    bool vld = i < M;
                    selfm[t] = vld ? smask[w * MPITCH + i] : 0u;
                    rowm[t]  = (vld && lane >= w && lane < ngroups)
                             ? smask[lane * MPITCH + i] : 0u;
                }
                #pragma unroll
                for (int t = 0; t < 8; ++t) {
                    int i = ibase + t;
                    if (i < M && kept < TOPK && !((cur >> ((sub * 8 + t) & 31)) & 1u)) {
                        if (lane == 0) sel[kept] = (short)i;
                        kept++;
                        cur |= selfm[t];
                        acc |= rowm[t];
                    }
                }
            }
        }
        if (lane == 0) s_nkept = kept;
    }
    __syncthreads();

    // ---- output ----
    const int n = s_nkept;
    const int fp = g_fp[lane_id];
    for (int r = tid; r < TOPK; r += 256) {
        float4 bb; float sc;
        if (r < n) {
            int i = sel[r];
            sc = sscore[i];
            bb = sbox[i];
        } else {
            sc = 0.0f;
            bb = __ldg((const float4*)(loc + ((size_t)b * NPRI + fp) * 4));
        }
        float* o = outp + r * 5;
        o[0] = sc; o[1] = bb.x; o[2] = bb.y; o[3] = bb.z; o[4] = bb.w;
    }
}

extern "C" void kernel_launch(void* const* d_in, const int* in_sizes, int n_in,
                              void* d_out, int out_size)
{
    const float* loc  = (const float*)d_in[0];   // [8, 8732, 4]
    const float* conf = (const float*)d_in[1];   // [8, 8732, 21]
    float* out = (float*)d_out;                  // [8, 21, 200, 5]

    static int configured = 0;
    if (!configured) {
        cudaFuncSetAttribute(k3_sweep_out,
                             cudaFuncAttributeMaxDynamicSharedMemorySize,
                             K3_SMEM_TOTAL);
        configured = 1;
    }
    k1_collect_sort<<<NLANES, 512>>>(loc, conf);
    k2_masks<<<dim3(NLANES, NSPLIT), 512>>>();
    k3_sweep_out<<<NLANES, 256, K3_SMEM_TOTAL>>>(loc, out);
}

// round 5
// speedup vs baseline: 5.6268x; 1.6674x over previous
#include <cuda_runtime.h>
#include <cuda_bf16.h>

#define NPRI    8732
#define NCLS    21
#define NBATCH  8
#define NLANES  (NBATCH * NCLS)   // 168
#define TOPK    200
#define MCAND   600
#define NGMAX   19                // ceil(MCAND/32)
#define MPITCH  601               // odd pitch -> conflict-free lane*MPITCH reads
#define CAP     1024
#define CONF_TH 0.95f
#define NMS_TH  0.45f
#define NTHREADS 512
#define NWARPS  16
#define G0      8                 // initial mask window: 256 candidates
#define GSTEP   4                 // extension step (rare path)

struct __align__(16) Smem {
    unsigned long long key[CAP];           // 8192 B
    float4             box[MCAND];         // 9600 B
    float              area[MCAND];        // 2400 B
    unsigned           mask[NGMAX * MPITCH]; // 45676 B  (mask[w*MPITCH + i])
    short              sel[TOPK];
    int                count, fp, nkept, done;
};

static __device__ __forceinline__ unsigned long long shfl_xor_u64(unsigned long long v, int m) {
    unsigned lo = __shfl_xor_sync(0xFFFFFFFFu, (unsigned)v, m);
    unsigned hi = __shfl_xor_sync(0xFFFFFFFFu, (unsigned)(v >> 32), m);
    return ((unsigned long long)hi << 32) | lo;
}

__global__ void __launch_bounds__(NTHREADS)
detect_kernel(const float* __restrict__ loc,
              const float* __restrict__ conf,
              float* __restrict__ out)
{
    extern __shared__ unsigned char raw[];
    Smem& S = *reinterpret_cast<Smem*>(raw);

    const int lane_id = blockIdx.x;
    const int b = lane_id / NCLS, c = lane_id % NCLS;
    float* outp = out + (size_t)lane_id * TOPK * 5;
    const int tid = threadIdx.x, lane = tid & 31, warp = tid >> 5;

    if (c == 0) {   // background class
        for (int i = tid; i < TOPK * 5; i += NTHREADS) outp[i] = 0.0f;
        return;
    }

    if (tid == 0) { S.count = 0; S.fp = 0x7FFFFFFF; }
    __syncthreads();

    // ================= Phase A: collect passers =================
    const float* confc = conf + (size_t)b * NPRI * NCLS + c;
    for (int base = 0; base < 18; base += 6) {          // 18*512 = 9216 >= 8732
        float sv[6];
        #pragma unroll
        for (int t = 0; t < 6; ++t) {
            int p = tid + (base + t) * NTHREADS;
            sv[t] = (p < NPRI) ? __ldg(&confc[(size_t)p * NCLS]) : 0.0f;
        }
        #pragma unroll
        for (int t = 0; t < 6; ++t) {
            int p = tid + (base + t) * NTHREADS;
            bool pass = sv[t] > CONF_TH;
            unsigned m = __ballot_sync(0xFFFFFFFFu, pass);
            if (m) {
                int leader = __ffs(m) - 1, bp = 0;
                if (lane == leader) {
                    bp = atomicAdd(&S.count, __popc(m));
                    atomicMin(&S.fp, p);
                }
                bp = __shfl_sync(0xFFFFFFFFu, bp, leader);
                if (pass) {
                    int pos = bp + __popc(m & ((1u << lane) - 1u));
                    if (pos < CAP)
                        S.key[pos] = ((unsigned long long)__float_as_uint(sv[t]) << 32)
                                   | (unsigned)(0xFFFFFFFFu - (unsigned)p);
                }
            }
        }
    }
    __syncthreads();
    const int count = min(S.count, CAP);
    if (count == 0) {
        for (int i = tid; i < TOPK * 5; i += NTHREADS) outp[i] = 0.0f;
        return;
    }

    // ================= Phase B: descending bitonic sort =================
    if (count <= 512) {
        unsigned long long v = (tid < count) ? S.key[tid] : 0ull;
        #pragma unroll
        for (int k = 2; k <= 32; k <<= 1) {
            #pragma unroll
            for (int j = k >> 1; j; j >>= 1) {
                unsigned long long o = shfl_xor_u64(v, j);
                bool takeMax = (((tid & k) == 0) == ((tid & j) == 0));
                bool gt = v > o;
                v = (takeMax == gt) ? v : o;
            }
        }
        S.key[tid] = v;
        #pragma unroll
        for (int k = 64; k <= 512; k <<= 1) {
            for (int j = k >> 1; j >= 32; j >>= 1) {
                __syncthreads();
                if ((tid & j) == 0) {
                    int l = tid ^ j;
                    unsigned long long a = S.key[tid], bb = S.key[l];
                    if (((tid & k) == 0) ? (a < bb) : (a > bb)) { S.key[tid] = bb; S.key[l] = a; }
                }
            }
            __syncthreads();
            v = S.key[tid];
            const bool up = ((tid & k) == 0);
            #pragma unroll
            for (int j = 16; j; j >>= 1) {
                unsigned long long o = shfl_xor_u64(v, j);
                bool takeMax = (up == ((tid & j) == 0));
                bool gt = v > o;
                v = (takeMax == gt) ? v : o;
            }
            S.key[tid] = v;
        }
        __syncthreads();
    } else {
        const int n2 = 1 << (32 - __clz(count - 1));
        for (int i = count + tid; i < n2; i += NTHREADS) S.key[i] = 0ull;
        for (int k = 2; k <= n2; k <<= 1) {
            for (int j = k >> 1; j > 0; j >>= 1) {
                __syncthreads();
                for (int i = tid; i < n2; i += NTHREADS) {
                    int l = i ^ j;
                    if (l > i) {
                        unsigned long long a = S.key[i], bb = S.key[l];
                        if (((i & k) == 0) ? (a < bb) : (a > bb)) { S.key[i] = bb; S.key[l] = a; }
                    }
                }
            }
        }
        __syncthreads();
    }

    // ================= Phase C: gather boxes =================
    const int M = min(count, MCAND);
    const int ngroups = (M + 31) >> 5;
    for (int t = tid; t < M; t += NTHREADS) {
        int p = (int)(0xFFFFFFFFu - (unsigned)(S.key[t] & 0xFFFFFFFFu));
        float4 L = __ldg((const float4*)(loc + ((size_t)b * NPRI + p) * 4));
        S.box[t]  = L;
        S.area[t] = (L.z - L.x) * (L.w - L.y);
    }
    __syncthreads();

    // ======== Phase D+E: adaptive mask window + greedy sweep ========
    int Gdone = 0;
    int target = min(ngroups, G0);
    int kept = 0;          // live in warp-0 registers across iterations
    unsigned acc = 0;

    while (true) {
        // ---- all warps: compute mask tiles for w in [Gdone,target), g in [0,w] ----
        {
            int tcnt = 0;
            for (int w = Gdone; w < target; ++w) {
                const int j0 = w * 32;
                const int jmax = min(32, M - j0);
                for (int g = 0; g <= w; ++g, ++tcnt) {
                    if ((tcnt & (NWARPS - 1)) != warp) continue;
                    const int i = g * 32 + lane;
                    const bool rv = i < M;
                    float4 bi = rv ? S.box[i] : make_float4(0, 0, 0, 0);
                    float  ai = rv ? S.area[i] : 0.0f;
                    unsigned bits = 0, uncb = 0;
                    #pragma unroll 8
                    for (int t2 = 0; t2 < jmax; ++t2) {
                        float4 bj = S.box[j0 + t2];
                        float  aj = S.area[j0 + t2];
                        float inter = fmaxf(fminf(bi.z, bj.z) - fmaxf(bi.x, bj.x), 0.0f)
                                    * fmaxf(fminf(bi.w, bj.w) - fmaxf(bi.y, bj.y), 0.0f);
                        float un = ai + aj - inter;
                        // division-free comparator for fdiv_rn(inter,un) > 0.45f
                        float d  = fmaf(-NMS_TH, un, inter);
                        float mg = fmaf(2e-6f, fabsf(inter) + fabsf(un), 1e-35f);
                        bool pos = un > 0.0f;
                        bool sup = pos ? (d > mg) : (d < -mg);
                        bool unc = !(fabsf(d) > mg) || (un == 0.0f);
                        if (sup) bits |= 1u << t2;
                        if (unc) uncb |= 1u << t2;
                    }
                    if (__ballot_sync(0xFFFFFFFFu, uncb != 0)) {   // rare exact fixup
                        while (uncb) {
                            int t2 = __ffs(uncb) - 1; uncb &= uncb - 1;
                            float4 bj = S.box[j0 + t2];
                            float  aj = S.area[j0 + t2];
                            float inter = fmaxf(fminf(bi.z, bj.z) - fmaxf(bi.x, bj.x), 0.0f)
                                        * fmaxf(fminf(bi.w, bj.w) - fmaxf(bi.y, bj.y), 0.0f);
                            float un = ai + aj - inter;
                            if (__fdiv_rn(inter, un) > NMS_TH) bits |= 1u << t2;
                        }
                    }
                    if (g == w) bits &= (0xFFFFFFFEu << lane);     // keep only j > i
                    if (rv) S.mask[w * MPITCH + i] = bits;
                }
            }
        }
        __syncthreads();

        // ---- warp 0: continue greedy sweep over rows [32*Gdone, 32*target) ----
        if (warp == 0) {
            if (Gdone > 0) {   // rebuild acc for newly available column words
                if (lane >= Gdone && lane < target) {
                    for (int k = 0; k < kept; ++k)
                        acc |= S.mask[lane * MPITCH + (int)S.sel[k]];
                }
            }
            for (int w = Gdone; w < target && kept < TOPK; ++w) {
                unsigned cur = __shfl_sync(0xFFFFFFFFu, acc, w);
                for (int sub = 0; sub < 4; ++sub) {
                    const int ibase = w * 32 + sub * 8;
                    if (ibase >= M) break;
                    unsigned selfm[8], rowm[8];
                    #pragma unroll
                    for (int t = 0; t < 8; ++t) {
                        int i = ibase + t;
                        bool vld = i < M;
                        selfm[t] = vld ? S.mask[w * MPITCH + i] : 0u;
                        rowm[t]  = (vld && lane >= w && lane < target)
                                 ? S.mask[lane * MPITCH + i] : 0u;
                    }
                    #pragma unroll
                    for (int t = 0; t < 8; ++t) {
                        int i = ibase + t;
                        if (i < M && kept < TOPK && !((cur >> ((sub * 8 + t) & 31)) & 1u)) {
                            if (lane == 0) S.sel[kept] = (short)i;
                            kept++;
                            cur |= selfm[t];
                            acc |= rowm[t];
                        }
                    }
                }
            }
            if (lane == 0) {
                S.nkept = kept;
                S.done  = (kept >= TOPK) || (target >= ngroups);
            }
        }
        __syncthreads();
        if (S.done) break;
        Gdone  = target;
        target = min(ngroups, target + GSTEP);
    }

    // ================= Phase F: output =================
    const int n = S.nkept;
    const int fp = S.fp;
    for (int r = tid; r < TOPK; r += NTHREADS) {
        float4 bb; float sc;
        if (r < n) {
            int i = S.sel[r];
            sc = __uint_as_float((unsigned)(S.key[i] >> 32));
            bb = S.box[i];
        } else {
            sc = 0.0f;
            bb = __ldg((const float4*)(loc + ((size_t)b * NPRI + fp) * 4));
        }
        float* o = outp + r * 5;
        o[0] = sc; o[1] = bb.x; o[2] = bb.y; o[3] = bb.z; o[4] = bb.w;
    }
}

extern "C" void kernel_launch(void* const* d_in, const int* in_sizes, int n_in,
                              void* d_out, int out_size)
{
    const float* loc  = (const float*)d_in[0];   // [8, 8732, 4]
    const float* conf = (const float*)d_in[1];   // [8, 8732, 21]
    float* out = (float*)d_out;                  // [8, 21, 200, 5]

    static int configured = 0;
    if (!configured) {
        cudaFuncSetAttribute(detect_kernel,
                             cudaFuncAttributeMaxDynamicSharedMemorySize,
                             (int)sizeof(Smem));
        configured = 1;
    }
    detect_kernel<<<NLANES, NTHREADS, sizeof(Smem)>>>(loc, conf, out);
}